// round 1
// baseline (speedup 1.0000x reference)
#include <cuda_runtime.h>

#define NN   50000
#define EE   1600000
#define HIDD 128
#define OUTD 64
#define NLL  200000
#define NEG  0.2f

// ---------------- device scratch (static, no allocation) ----------------
__device__ float g_hA[NN * HIDD];     // 25.6 MB  ping
__device__ float g_hB[NN * HIDD];     // 25.6 MB  pong
__device__ float g_es[NN];
__device__ float g_ed[NN];
__device__ float g_z[NN * OUTD];      // 12.8 MB final node embeddings
__device__ int   g_cnt[NN];
__device__ int   g_rowptr[NN + 1];
__device__ int   g_wptr[NN];
__device__ int   g_col[EE];           // src ids sorted by dst
__device__ float g_dinv[NN];

__device__ __forceinline__ float leaky(float v) { return v > 0.f ? v : NEG * v; }

// ---------------- CSR construction ----------------
__global__ void zero_cnt_k() {
    int i = blockIdx.x * blockDim.x + threadIdx.x;
    if (i < NN) g_cnt[i] = 0;
}

__global__ void count_k(const int* __restrict__ dst) {
    int e = blockIdx.x * blockDim.x + threadIdx.x;
    if (e < EE) atomicAdd(&g_cnt[dst[e]], 1);
}

// single-block exclusive scan over 50001 entries + dinv = rsqrt(indeg+1)
__global__ void scan_k() {
    __shared__ int sh[1024];
    __shared__ int carry;
    int tid = threadIdx.x;
    if (tid == 0) { carry = 0; g_rowptr[0] = 0; }
    __syncthreads();
    for (int base = 0; base < NN; base += 1024) {
        int i = base + tid;
        int v = (i < NN) ? g_cnt[i] : 0;
        sh[tid] = v;
        __syncthreads();
        for (int off = 1; off < 1024; off <<= 1) {
            int t = (tid >= off) ? sh[tid - off] : 0;
            __syncthreads();
            sh[tid] += t;
            __syncthreads();
        }
        if (i < NN) {
            g_rowptr[i + 1] = sh[tid] + carry;
            g_dinv[i] = rsqrtf((float)v + 1.0f);
        }
        __syncthreads();
        if (tid == 0) carry += sh[1023];
        __syncthreads();
    }
}

__global__ void wptr_k() {
    int i = blockIdx.x * blockDim.x + threadIdx.x;
    if (i < NN) g_wptr[i] = g_rowptr[i];
}

__global__ void scatter_k(const int* __restrict__ src, const int* __restrict__ dst) {
    int e = blockIdx.x * blockDim.x + threadIdx.x;
    if (e < EE) {
        int p = atomicAdd(&g_wptr[dst[e]], 1);
        g_col[p] = src[e];
    }
}

// ---------------- GEMM (warp per row) + attention scalars ----------------
__global__ void gemm_gat_k(const float* __restrict__ X, const float* __restrict__ W,
                           const float* __restrict__ a_s, const float* __restrict__ a_d,
                           float* __restrict__ H) {
    __shared__ float sx[8][HIDD];
    int warp = threadIdx.x >> 5, lane = threadIdx.x & 31;
    int row = blockIdx.x * 8 + warp;
    if (row >= NN) return;
    const float* xr = X + (size_t)row * HIDD;
    for (int t = lane; t < HIDD; t += 32) sx[warp][t] = xr[t];
    __syncwarp();

    float4 acc = make_float4(0.f, 0.f, 0.f, 0.f);
#pragma unroll 8
    for (int k = 0; k < HIDD; k++) {
        float xk = sx[warp][k];
        float4 w = *(const float4*)(W + k * HIDD + lane * 4);
        acc.x += xk * w.x; acc.y += xk * w.y;
        acc.z += xk * w.z; acc.w += xk * w.w;
    }
    *(float4*)(H + (size_t)row * HIDD + lane * 4) = acc;

    float4 a4 = *(const float4*)(a_s + lane * 4);
    float4 d4 = *(const float4*)(a_d + lane * 4);
    float es = acc.x * a4.x + acc.y * a4.y + acc.z * a4.z + acc.w * a4.w;
    float ed = acc.x * d4.x + acc.y * d4.y + acc.z * d4.z + acc.w * d4.w;
#pragma unroll
    for (int o = 16; o; o >>= 1) {
        es += __shfl_xor_sync(0xffffffff, es, o);
        ed += __shfl_xor_sync(0xffffffff, ed, o);
    }
    if (lane == 0) { g_es[row] = es; g_ed[row] = ed; }
}

// ---------------- GAT aggregation: warp per dst node, 2 passes ----------------
__global__ void agg_gat_k(const float* __restrict__ H, float* __restrict__ Ho,
                          const float* __restrict__ bias) {
    int warp = threadIdx.x >> 5, lane = threadIdx.x & 31;
    int i = blockIdx.x * 8 + warp;
    if (i >= NN) return;
    int r0 = g_rowptr[i], r1 = g_rowptr[i + 1];
    float edi = g_ed[i];
    float eself = leaky(g_es[i] + edi);

    // pass 1: segment max (lanes stride neighbors)
    float m = eself;
    for (int j = r0 + lane; j < r1; j += 32)
        m = fmaxf(m, leaky(g_es[g_col[j]] + edi));
#pragma unroll
    for (int o = 16; o; o >>= 1) m = fmaxf(m, __shfl_xor_sync(0xffffffff, m, o));

    // pass 2: fused exp-sum + weighted accumulate (self loop first)
    float p = __expf(eself - m);
    float s = p;
    float4 hv = *(const float4*)(H + (size_t)i * HIDD + lane * 4);
    float4 acc;
    acc.x = p * hv.x; acc.y = p * hv.y; acc.z = p * hv.z; acc.w = p * hv.w;

#pragma unroll 4
    for (int j = r0; j < r1; j++) {
        int src = g_col[j];
        float pj = __expf(leaky(g_es[src] + edi) - m);
        s += pj;
        float4 h2 = *(const float4*)(H + (size_t)src * HIDD + lane * 4);
        acc.x += pj * h2.x; acc.y += pj * h2.y;
        acc.z += pj * h2.z; acc.w += pj * h2.w;
    }
    float inv = 1.0f / s;
    float4 b4 = *(const float4*)(bias + lane * 4);
    acc.x = fmaxf(acc.x * inv + b4.x, 0.f);
    acc.y = fmaxf(acc.y * inv + b4.y, 0.f);
    acc.z = fmaxf(acc.z * inv + b4.z, 0.f);
    acc.w = fmaxf(acc.w * inv + b4.w, 0.f);
    *(float4*)(Ho + (size_t)i * HIDD + lane * 4) = acc;
}

// ---------------- GCN: GEMM 128->64 and normalized aggregation ----------------
__global__ void gemm_gcn_k(const float* __restrict__ X, const float* __restrict__ W,
                           float* __restrict__ H) {
    __shared__ float sx[8][HIDD];
    int warp = threadIdx.x >> 5, lane = threadIdx.x & 31;
    int row = blockIdx.x * 8 + warp;
    if (row >= NN) return;
    const float* xr = X + (size_t)row * HIDD;
    for (int t = lane; t < HIDD; t += 32) sx[warp][t] = xr[t];
    __syncwarp();

    float2 acc = make_float2(0.f, 0.f);
#pragma unroll 8
    for (int k = 0; k < HIDD; k++) {
        float xk = sx[warp][k];
        float2 w = *(const float2*)(W + k * OUTD + lane * 2);
        acc.x += xk * w.x; acc.y += xk * w.y;
    }
    *(float2*)(H + (size_t)row * OUTD + lane * 2) = acc;
}

__global__ void agg_gcn_k(const float* __restrict__ G, const float* __restrict__ b4) {
    int warp = threadIdx.x >> 5, lane = threadIdx.x & 31;
    int i = blockIdx.x * 8 + warp;
    if (i >= NN) return;
    int r0 = g_rowptr[i], r1 = g_rowptr[i + 1];
    float di = g_dinv[i];

    float2 gi = *(const float2*)(G + (size_t)i * OUTD + lane * 2);
    float w0 = di * di;  // self loop
    float2 acc; acc.x = w0 * gi.x; acc.y = w0 * gi.y;

#pragma unroll 4
    for (int j = r0; j < r1; j++) {
        int src = g_col[j];
        float w = di * g_dinv[src];
        float2 gs = *(const float2*)(G + (size_t)src * OUTD + lane * 2);
        acc.x += w * gs.x; acc.y += w * gs.y;
    }
    float2 bb = *(const float2*)(b4 + lane * 2);
    acc.x += bb.x; acc.y += bb.y;
    *(float2*)(g_z + (size_t)i * OUTD + lane * 2) = acc;
}

// ---------------- link decode: warp per label edge ----------------
__global__ void decode_k(const int* __restrict__ eli, float* __restrict__ out) {
    int warp = threadIdx.x >> 5, lane = threadIdx.x & 31;
    int l = blockIdx.x * 8 + warp;
    if (l >= NLL) return;
    int a = eli[l], b = eli[NLL + l];
    float2 za = *(const float2*)(g_z + (size_t)a * OUTD + lane * 2);
    float2 zb = *(const float2*)(g_z + (size_t)b * OUTD + lane * 2);
    float d = za.x * zb.x + za.y * zb.y;
#pragma unroll
    for (int o = 16; o; o >>= 1) d += __shfl_xor_sync(0xffffffff, d, o);
    if (lane == 0) out[l] = d;
}

// ---------------- launch ----------------
extern "C" void kernel_launch(void* const* d_in, const int* in_sizes, int n_in,
                              void* d_out, int out_size) {
    const float* x    = (const float*)d_in[0];
    const int*   ei   = (const int*)d_in[1];
    const int*   eli  = (const int*)d_in[2];
    const float* W1  = (const float*)d_in[3];
    const float* a1s = (const float*)d_in[4];
    const float* a1d = (const float*)d_in[5];
    const float* b1  = (const float*)d_in[6];
    const float* W2  = (const float*)d_in[7];
    const float* a2s = (const float*)d_in[8];
    const float* a2d = (const float*)d_in[9];
    const float* b2  = (const float*)d_in[10];
    const float* W3  = (const float*)d_in[11];
    const float* a3s = (const float*)d_in[12];
    const float* a3d = (const float*)d_in[13];
    const float* b3  = (const float*)d_in[14];
    const float* W4  = (const float*)d_in[15];
    const float* b4  = (const float*)d_in[16];

    float *hA, *hB;
    cudaGetSymbolAddress((void**)&hA, g_hA);
    cudaGetSymbolAddress((void**)&hB, g_hB);

    const int* src = ei;
    const int* dst = ei + EE;

    // CSR build
    zero_cnt_k<<<(NN + 255) / 256, 256>>>();
    count_k<<<(EE + 255) / 256, 256>>>(dst);
    scan_k<<<1, 1024>>>();
    wptr_k<<<(NN + 255) / 256, 256>>>();
    scatter_k<<<(EE + 255) / 256, 256>>>(src, dst);

    int gb = (NN + 7) / 8;   // warp-per-row/node kernels, 8 warps per block

    // GAT layer 1
    gemm_gat_k<<<gb, 256>>>(x,  W1, a1s, a1d, hA);
    agg_gat_k <<<gb, 256>>>(hA, hB, b1);
    // GAT layer 2
    gemm_gat_k<<<gb, 256>>>(hB, W2, a2s, a2d, hA);
    agg_gat_k <<<gb, 256>>>(hA, hB, b2);
    // GAT layer 3
    gemm_gat_k<<<gb, 256>>>(hB, W3, a3s, a3d, hA);
    agg_gat_k <<<gb, 256>>>(hA, hB, b3);
    // GCN layer (reuse hA as [N,64] pre-aggregation buffer)
    gemm_gcn_k<<<gb, 256>>>(hB, W4, hA);
    agg_gcn_k <<<gb, 256>>>(hA, b4);
    // decode
    decode_k<<<(NLL + 7) / 8, 256>>>(eli, (float*)d_out);
}

// round 2
// speedup vs baseline: 1.2967x; 1.2967x over previous
#include <cuda_runtime.h>

#define NN   50000
#define EE   1600000
#define HIDD 128
#define OUTD 64
#define NLL  200000
#define NEG  0.2f

// ---------------- device scratch (static, no allocation) ----------------
__device__ float g_hA[NN * HIDD];
__device__ float g_hB[NN * HIDD];
__device__ float g_es[NN];
__device__ float g_ed[NN];
__device__ float g_z[NN * OUTD];
__device__ int   g_cnt[NN];
__device__ int   g_rowptr[NN + 1];
__device__ int   g_wptr[NN];
__device__ int   g_col[EE];
__device__ float g_dinv[NN];

__device__ __forceinline__ float leaky(float v) { return v > 0.f ? v : NEG * v; }

// ---------------- CSR construction ----------------
__global__ void zero_cnt_k() {
    int i = blockIdx.x * blockDim.x + threadIdx.x;
    if (i < NN) g_cnt[i] = 0;
}

__global__ void count_k(const int* __restrict__ dst) {
    int e = blockIdx.x * blockDim.x + threadIdx.x;
    if (e < EE) atomicAdd(&g_cnt[dst[e]], 1);
}

// single-block warp-shuffle scan; also writes g_wptr and g_dinv (fuses wptr_k)
__global__ void scan_k() {
    __shared__ int s_warp[32];
    __shared__ int s_carry;
    int tid = threadIdx.x;
    int wid = tid >> 5, lane = tid & 31;
    if (tid == 0) { s_carry = 0; g_rowptr[0] = 0; }
    __syncthreads();
    for (int base = 0; base < NN; base += 1024) {
        int i = base + tid;
        int c = s_carry;
        int v0 = (i < NN) ? g_cnt[i] : 0;
        int v = v0;
        // inclusive warp scan
#pragma unroll
        for (int off = 1; off < 32; off <<= 1) {
            int t = __shfl_up_sync(0xffffffff, v, off);
            if (lane >= off) v += t;
        }
        if (lane == 31) s_warp[wid] = v;
        __syncthreads();
        if (wid == 0) {
            int w = s_warp[lane];
#pragma unroll
            for (int off = 1; off < 32; off <<= 1) {
                int t = __shfl_up_sync(0xffffffff, w, off);
                if (lane >= off) w += t;
            }
            s_warp[lane] = w;
        }
        __syncthreads();
        int incl = v + (wid > 0 ? s_warp[wid - 1] : 0) + c;
        if (i < NN) {
            g_rowptr[i + 1] = incl;
            g_wptr[i] = incl - v0;
            g_dinv[i] = rsqrtf((float)v0 + 1.0f);
        }
        if (tid == 0) s_carry = c + s_warp[31];
        __syncthreads();
    }
}

__global__ void scatter_k(const int* __restrict__ src, const int* __restrict__ dst) {
    int e = blockIdx.x * blockDim.x + threadIdx.x;
    if (e < EE) {
        int p = atomicAdd(&g_wptr[dst[e]], 1);
        g_col[p] = src[e];
    }
}

// ---------------- GAT GEMM: warp computes 4 rows x 128 cols ----------------
__global__ void gemm_gat_k(const float* __restrict__ X, const float* __restrict__ W,
                           const float* __restrict__ a_s, const float* __restrict__ a_d,
                           float* __restrict__ H) {
    __shared__ float sx[8][4 * HIDD];
    int warp = threadIdx.x >> 5, lane = threadIdx.x & 31;
    int row0 = (blockIdx.x * 8 + warp) * 4;
    if (row0 >= NN) return;
    int nrows = NN - row0; if (nrows > 4) nrows = 4;

    // cooperative load of up to 4 rows (each row = 32 float4)
    for (int t = lane; t < nrows * 32; t += 32)
        ((float4*)sx[warp])[t] = ((const float4*)(X + (size_t)row0 * HIDD))[t];
    __syncwarp();

    float4 acc0 = {0,0,0,0}, acc1 = acc0, acc2 = acc0, acc3 = acc0;
#pragma unroll 4
    for (int k = 0; k < HIDD; k++) {
        float4 w = *(const float4*)(W + k * HIDD + lane * 4);
        float x0 = sx[warp][k];
        float x1 = sx[warp][HIDD + k];
        float x2 = sx[warp][2 * HIDD + k];
        float x3 = sx[warp][3 * HIDD + k];
        acc0.x += x0 * w.x; acc0.y += x0 * w.y; acc0.z += x0 * w.z; acc0.w += x0 * w.w;
        acc1.x += x1 * w.x; acc1.y += x1 * w.y; acc1.z += x1 * w.z; acc1.w += x1 * w.w;
        acc2.x += x2 * w.x; acc2.y += x2 * w.y; acc2.z += x2 * w.z; acc2.w += x2 * w.w;
        acc3.x += x3 * w.x; acc3.y += x3 * w.y; acc3.z += x3 * w.z; acc3.w += x3 * w.w;
    }

    float4 a4 = *(const float4*)(a_s + lane * 4);
    float4 d4 = *(const float4*)(a_d + lane * 4);
    float4 accs[4] = {acc0, acc1, acc2, acc3};
#pragma unroll
    for (int r = 0; r < 4; r++) {
        if (r >= nrows) break;
        float4 a = accs[r];
        *(float4*)(H + (size_t)(row0 + r) * HIDD + lane * 4) = a;
        float es = a.x * a4.x + a.y * a4.y + a.z * a4.z + a.w * a4.w;
        float ed = a.x * d4.x + a.y * d4.y + a.z * d4.z + a.w * d4.w;
#pragma unroll
        for (int o = 16; o; o >>= 1) {
            es += __shfl_xor_sync(0xffffffff, es, o);
            ed += __shfl_xor_sync(0xffffffff, ed, o);
        }
        if (lane == 0) { g_es[row0 + r] = es; g_ed[row0 + r] = ed; }
    }
}

// ---------------- GAT aggregation: warp per dst node ----------------
// leaky is monotone increasing -> segment max = leaky(max(es)+edi).
// exp computed lane-parallel (one MUFU per 32 edges), redistributed via shfl.
__global__ void agg_gat_k(const float* __restrict__ H, float* __restrict__ Ho,
                          const float* __restrict__ bias) {
    int warp = threadIdx.x >> 5, lane = threadIdx.x & 31;
    int i = blockIdx.x * 8 + warp;
    if (i >= NN) return;
    int r0 = g_rowptr[i], r1 = g_rowptr[i + 1];
    float edi = g_ed[i];
    float esi = g_es[i];

    // pass 1: max of es over neighbor sources (+ self)
    float mes = esi;
    for (int j = r0 + lane; j < r1; j += 32)
        mes = fmaxf(mes, g_es[g_col[j]]);
#pragma unroll
    for (int o = 16; o; o >>= 1) mes = fmaxf(mes, __shfl_xor_sync(0xffffffff, mes, o));
    float m = leaky(mes + edi);

    // self contribution
    float p0 = __expf(leaky(esi + edi) - m);
    float4 hv = *(const float4*)(H + (size_t)i * HIDD + lane * 4);
    float4 acc;
    acc.x = p0 * hv.x; acc.y = p0 * hv.y; acc.z = p0 * hv.z; acc.w = p0 * hv.w;
    float spart = 0.f;

    // pass 2: chunks of 32 edges; lane-parallel exp, shfl-redistribute
    for (int base = r0; base < r1; base += 32) {
        int j = base + lane;
        int src = 0; float pj = 0.f;
        if (j < r1) {
            src = g_col[j];
            pj = __expf(leaky(g_es[src] + edi) - m);
            spart += pj;
        }
        int cnt = r1 - base; if (cnt > 32) cnt = 32;
#pragma unroll 4
        for (int t = 0; t < cnt; t++) {
            float p = __shfl_sync(0xffffffff, pj, t);
            int sj  = __shfl_sync(0xffffffff, src, t);
            float4 h2 = *(const float4*)(H + (size_t)sj * HIDD + lane * 4);
            acc.x += p * h2.x; acc.y += p * h2.y;
            acc.z += p * h2.z; acc.w += p * h2.w;
        }
    }
#pragma unroll
    for (int o = 16; o; o >>= 1) spart += __shfl_xor_sync(0xffffffff, spart, o);
    float inv = 1.0f / (p0 + spart);

    float4 b4 = *(const float4*)(bias + lane * 4);
    acc.x = fmaxf(acc.x * inv + b4.x, 0.f);
    acc.y = fmaxf(acc.y * inv + b4.y, 0.f);
    acc.z = fmaxf(acc.z * inv + b4.z, 0.f);
    acc.w = fmaxf(acc.w * inv + b4.w, 0.f);
    *(float4*)(Ho + (size_t)i * HIDD + lane * 4) = acc;
}

// ---------------- GCN GEMM: warp computes 4 rows x 64 cols ----------------
__global__ void gemm_gcn_k(const float* __restrict__ X, const float* __restrict__ W,
                           float* __restrict__ H) {
    __shared__ float sx[8][4 * HIDD];
    int warp = threadIdx.x >> 5, lane = threadIdx.x & 31;
    int row0 = (blockIdx.x * 8 + warp) * 4;
    if (row0 >= NN) return;
    int nrows = NN - row0; if (nrows > 4) nrows = 4;

    for (int t = lane; t < nrows * 32; t += 32)
        ((float4*)sx[warp])[t] = ((const float4*)(X + (size_t)row0 * HIDD))[t];
    __syncwarp();

    float2 acc0 = {0,0}, acc1 = acc0, acc2 = acc0, acc3 = acc0;
#pragma unroll 4
    for (int k = 0; k < HIDD; k++) {
        float2 w = *(const float2*)(W + k * OUTD + lane * 2);
        float x0 = sx[warp][k];
        float x1 = sx[warp][HIDD + k];
        float x2 = sx[warp][2 * HIDD + k];
        float x3 = sx[warp][3 * HIDD + k];
        acc0.x += x0 * w.x; acc0.y += x0 * w.y;
        acc1.x += x1 * w.x; acc1.y += x1 * w.y;
        acc2.x += x2 * w.x; acc2.y += x2 * w.y;
        acc3.x += x3 * w.x; acc3.y += x3 * w.y;
    }
    float2 accs[4] = {acc0, acc1, acc2, acc3};
#pragma unroll
    for (int r = 0; r < 4; r++) {
        if (r >= nrows) break;
        *(float2*)(H + (size_t)(row0 + r) * OUTD + lane * 2) = accs[r];
    }
}

__global__ void agg_gcn_k(const float* __restrict__ G, const float* __restrict__ b4) {
    int warp = threadIdx.x >> 5, lane = threadIdx.x & 31;
    int i = blockIdx.x * 8 + warp;
    if (i >= NN) return;
    int r0 = g_rowptr[i], r1 = g_rowptr[i + 1];
    float di = g_dinv[i];

    float2 gi = *(const float2*)(G + (size_t)i * OUTD + lane * 2);
    float w0 = di * di;
    float2 acc; acc.x = w0 * gi.x; acc.y = w0 * gi.y;

    for (int base = r0; base < r1; base += 32) {
        int j = base + lane;
        int src = 0; float wj = 0.f;
        if (j < r1) {
            src = g_col[j];
            wj = di * g_dinv[src];
        }
        int cnt = r1 - base; if (cnt > 32) cnt = 32;
#pragma unroll 4
        for (int t = 0; t < cnt; t++) {
            float w = __shfl_sync(0xffffffff, wj, t);
            int sj  = __shfl_sync(0xffffffff, src, t);
            float2 gs = *(const float2*)(G + (size_t)sj * OUTD + lane * 2);
            acc.x += w * gs.x; acc.y += w * gs.y;
        }
    }
    float2 bb = *(const float2*)(b4 + lane * 2);
    acc.x += bb.x; acc.y += bb.y;
    *(float2*)(g_z + (size_t)i * OUTD + lane * 2) = acc;
}

// ---------------- link decode: warp per label edge ----------------
__global__ void decode_k(const int* __restrict__ eli, float* __restrict__ out) {
    int warp = threadIdx.x >> 5, lane = threadIdx.x & 31;
    int l = blockIdx.x * 8 + warp;
    if (l >= NLL) return;
    int a = eli[l], b = eli[NLL + l];
    float2 za = *(const float2*)(g_z + (size_t)a * OUTD + lane * 2);
    float2 zb = *(const float2*)(g_z + (size_t)b * OUTD + lane * 2);
    float d = za.x * zb.x + za.y * zb.y;
#pragma unroll
    for (int o = 16; o; o >>= 1) d += __shfl_xor_sync(0xffffffff, d, o);
    if (lane == 0) out[l] = d;
}

// ---------------- launch ----------------
extern "C" void kernel_launch(void* const* d_in, const int* in_sizes, int n_in,
                              void* d_out, int out_size) {
    const float* x    = (const float*)d_in[0];
    const int*   ei   = (const int*)d_in[1];
    const int*   eli  = (const int*)d_in[2];
    const float* W1  = (const float*)d_in[3];
    const float* a1s = (const float*)d_in[4];
    const float* a1d = (const float*)d_in[5];
    const float* b1  = (const float*)d_in[6];
    const float* W2  = (const float*)d_in[7];
    const float* a2s = (const float*)d_in[8];
    const float* a2d = (const float*)d_in[9];
    const float* b2  = (const float*)d_in[10];
    const float* W3  = (const float*)d_in[11];
    const float* a3s = (const float*)d_in[12];
    const float* a3d = (const float*)d_in[13];
    const float* b3  = (const float*)d_in[14];
    const float* W4  = (const float*)d_in[15];
    const float* b4  = (const float*)d_in[16];

    float *hA, *hB;
    cudaGetSymbolAddress((void**)&hA, g_hA);
    cudaGetSymbolAddress((void**)&hB, g_hB);

    const int* src = ei;
    const int* dst = ei + EE;

    // CSR build
    zero_cnt_k<<<(NN + 255) / 256, 256>>>();
    count_k<<<(EE + 255) / 256, 256>>>(dst);
    scan_k<<<1, 1024>>>();
    scatter_k<<<(EE + 255) / 256, 256>>>(src, dst);

    int gb_gemm = (NN + 31) / 32;  // 8 warps x 4 rows per block
    int gb_node = (NN + 7) / 8;    // warp per node

    gemm_gat_k<<<gb_gemm, 256>>>(x,  W1, a1s, a1d, hA);
    agg_gat_k <<<gb_node, 256>>>(hA, hB, b1);
    gemm_gat_k<<<gb_gemm, 256>>>(hB, W2, a2s, a2d, hA);
    agg_gat_k <<<gb_node, 256>>>(hA, hB, b2);
    gemm_gat_k<<<gb_gemm, 256>>>(hB, W3, a3s, a3d, hA);
    agg_gat_k <<<gb_node, 256>>>(hA, hB, b3);
    gemm_gcn_k<<<gb_gemm, 256>>>(hB, W4, hA);
    agg_gcn_k <<<gb_node, 256>>>(hA, b4);
    decode_k<<<(NLL + 7) / 8, 256>>>(eli, (float*)d_out);
}

// round 4
// speedup vs baseline: 1.3037x; 1.0054x over previous
#include <cuda_runtime.h>
#include <cuda_fp16.h>

#define NN   50000
#define EE   1600000
#define HIDD 128
#define OUTD 64
#define NLL  200000
#define NEG  0.2f

// ---------------- device scratch (static, no allocation) ----------------
__device__ float   g_hF[NN * HIDD];      // fp32 layer input (agg output)
__device__ __half2 g_h16[NN * (HIDD/2)]; // fp16 gather copy of h
__device__ __half2 g_g16[NN * (OUTD/2)]; // fp16 GCN pre-agg features
__device__ float   g_es[NN];
__device__ float   g_ed[NN];
__device__ float   g_z[NN * OUTD];
__device__ int     g_cnt[NN];
__device__ int     g_rowptr[NN + 1];
__device__ int     g_wptr[NN];
__device__ int     g_col[EE];
__device__ float   g_dinv[NN];

__device__ __forceinline__ float leaky(float v) { return v > 0.f ? v : NEG * v; }

typedef unsigned long long u64;
__device__ __forceinline__ u64 pack2(float lo, float hi) {
    u64 r; asm("mov.b64 %0, {%1, %2};" : "=l"(r) : "f"(lo), "f"(hi)); return r;
}
__device__ __forceinline__ float2 unpack2(u64 v) {
    float2 f; asm("mov.b64 {%0, %1}, %2;" : "=f"(f.x), "=f"(f.y) : "l"(v)); return f;
}
#define FMA2(d, a, b) asm("fma.rn.f32x2 %0, %1, %2, %0;" : "+l"(d) : "l"(a), "l"(b))

// ---------------- CSR construction ----------------
__global__ void zero_cnt_k() {
    int i = blockIdx.x * blockDim.x + threadIdx.x;
    if (i < NN) g_cnt[i] = 0;
}

__global__ void count_k(const int* __restrict__ dst) {
    int e = blockIdx.x * blockDim.x + threadIdx.x;
    if (e < EE) atomicAdd(&g_cnt[dst[e]], 1);
}

// single-block warp-shuffle scan; also writes g_wptr and g_dinv
__global__ void scan_k() {
    __shared__ int s_warp[32];
    __shared__ int s_carry;
    int tid = threadIdx.x;
    int wid = tid >> 5, lane = tid & 31;
    if (tid == 0) { s_carry = 0; g_rowptr[0] = 0; }
    __syncthreads();
    for (int base = 0; base < NN; base += 1024) {
        int i = base + tid;
        int c = s_carry;
        int v0 = (i < NN) ? g_cnt[i] : 0;
        int v = v0;
#pragma unroll
        for (int off = 1; off < 32; off <<= 1) {
            int t = __shfl_up_sync(0xffffffff, v, off);
            if (lane >= off) v += t;
        }
        if (lane == 31) s_warp[wid] = v;
        __syncthreads();
        if (wid == 0) {
            int w = s_warp[lane];
#pragma unroll
            for (int off = 1; off < 32; off <<= 1) {
                int t = __shfl_up_sync(0xffffffff, w, off);
                if (lane >= off) w += t;
            }
            s_warp[lane] = w;
        }
        __syncthreads();
        int incl = v + (wid > 0 ? s_warp[wid - 1] : 0) + c;
        if (i < NN) {
            g_rowptr[i + 1] = incl;
            g_wptr[i] = incl - v0;
            g_dinv[i] = rsqrtf((float)v0 + 1.0f);
        }
        if (tid == 0) s_carry = c + s_warp[31];
        __syncthreads();
    }
}

__global__ void scatter_k(const int* __restrict__ src, const int* __restrict__ dst) {
    int e = blockIdx.x * blockDim.x + threadIdx.x;
    if (e < EE) {
        int p = atomicAdd(&g_wptr[dst[e]], 1);
        g_col[p] = src[e];
    }
}

// ---------------- GAT GEMM: warp computes 4 rows x 128 cols, f32x2 FMA ----------------
__global__ void gemm_gat_k(const float* __restrict__ X, const float* __restrict__ W,
                           const float* __restrict__ a_s, const float* __restrict__ a_d) {
    __shared__ float2 sx[8][4 * HIDD];   // x values duplicated into pairs (32KB/block)
    int warp = threadIdx.x >> 5, lane = threadIdx.x & 31;
    int row0 = (blockIdx.x * 8 + warp) * 4;
    if (row0 >= NN) return;

    // fill duplicated x pairs
    for (int t = lane; t < 4 * HIDD; t += 32) {
        float v = X[(size_t)row0 * HIDD + t];
        sx[warp][t] = make_float2(v, v);
    }
    __syncwarp();

    u64 a0p0 = 0, a0p1 = 0, a1p0 = 0, a1p1 = 0;
    u64 a2p0 = 0, a2p1 = 0, a3p0 = 0, a3p1 = 0;
    const u64* sx0 = (const u64*)&sx[warp][0];
    const u64* sx1 = (const u64*)&sx[warp][HIDD];
    const u64* sx2p = (const u64*)&sx[warp][2 * HIDD];
    const u64* sx3 = (const u64*)&sx[warp][3 * HIDD];
#pragma unroll 4
    for (int k = 0; k < HIDD; k++) {
        float4 w = *(const float4*)(W + k * HIDD + lane * 4);
        u64 wp0 = pack2(w.x, w.y);
        u64 wp1 = pack2(w.z, w.w);
        u64 x0 = sx0[k], x1 = sx1[k], x2 = sx2p[k], x3 = sx3[k];
        FMA2(a0p0, x0, wp0); FMA2(a0p1, x0, wp1);
        FMA2(a1p0, x1, wp0); FMA2(a1p1, x1, wp1);
        FMA2(a2p0, x2, wp0); FMA2(a2p1, x2, wp1);
        FMA2(a3p0, x3, wp0); FMA2(a3p1, x3, wp1);
    }

    float4 a4 = *(const float4*)(a_s + lane * 4);
    float4 d4 = *(const float4*)(a_d + lane * 4);
    u64 accs[8] = {a0p0, a0p1, a1p0, a1p1, a2p0, a2p1, a3p0, a3p1};
#pragma unroll
    for (int r = 0; r < 4; r++) {
        float2 lo = unpack2(accs[2 * r]);
        float2 hi = unpack2(accs[2 * r + 1]);
        // fp16 gather copy
        __half2 h0 = __floats2half2_rn(lo.x, lo.y);
        __half2 h1 = __floats2half2_rn(hi.x, hi.y);
        uint2 st; st.x = *(unsigned*)&h0; st.y = *(unsigned*)&h1;
        *(uint2*)(g_h16 + (size_t)(row0 + r) * (HIDD/2) + lane * 2) = st;
        // attention scalars from exact fp32
        float es = lo.x * a4.x + lo.y * a4.y + hi.x * a4.z + hi.y * a4.w;
        float ed = lo.x * d4.x + lo.y * d4.y + hi.x * d4.z + hi.y * d4.w;
#pragma unroll
        for (int o = 16; o; o >>= 1) {
            es += __shfl_xor_sync(0xffffffff, es, o);
            ed += __shfl_xor_sync(0xffffffff, ed, o);
        }
        if (lane == 0) { g_es[row0 + r] = es; g_ed[row0 + r] = ed; }
    }
}

// ---------------- GAT aggregation: warp per dst node, fp16 gather ----------------
__global__ void agg_gat_k(const float* __restrict__ bias, float* __restrict__ Ho) {
    int warp = threadIdx.x >> 5, lane = threadIdx.x & 31;
    int i = blockIdx.x * 8 + warp;
    if (i >= NN) return;
    int r0 = g_rowptr[i], r1 = g_rowptr[i + 1];
    float edi = g_ed[i];
    float esi = g_es[i];

    // pass 1: max of es over sources (+ self); leaky monotone
    float mes = esi;
    for (int j = r0 + lane; j < r1; j += 32)
        mes = fmaxf(mes, g_es[g_col[j]]);
#pragma unroll
    for (int o = 16; o; o >>= 1) mes = fmaxf(mes, __shfl_xor_sync(0xffffffff, mes, o));
    float m = leaky(mes + edi);

    // self contribution
    float p0 = __expf(leaky(esi + edi) - m);
    uint2 hv = *(const uint2*)(g_h16 + (size_t)i * (HIDD/2) + lane * 2);
    float2 f0 = __half22float2(*(__half2*)&hv.x);
    float2 f1 = __half22float2(*(__half2*)&hv.y);
    float4 acc;
    acc.x = p0 * f0.x; acc.y = p0 * f0.y; acc.z = p0 * f1.x; acc.w = p0 * f1.y;
    float spart = 0.f;

    // pass 2: 32-edge chunks, lane-parallel exp, shfl redistribute
    for (int base = r0; base < r1; base += 32) {
        int j = base + lane;
        int src = 0; float pj = 0.f;
        if (j < r1) {
            src = g_col[j];
            pj = __expf(leaky(g_es[src] + edi) - m);
            spart += pj;
        }
        int cnt = r1 - base; if (cnt > 32) cnt = 32;
#pragma unroll 4
        for (int t = 0; t < cnt; t++) {
            float p = __shfl_sync(0xffffffff, pj, t);
            int sj  = __shfl_sync(0xffffffff, src, t);
            uint2 h2 = *(const uint2*)(g_h16 + (size_t)sj * (HIDD/2) + lane * 2);
            float2 g0 = __half22float2(*(__half2*)&h2.x);
            float2 g1 = __half22float2(*(__half2*)&h2.y);
            acc.x += p * g0.x; acc.y += p * g0.y;
            acc.z += p * g1.x; acc.w += p * g1.y;
        }
    }
#pragma unroll
    for (int o = 16; o; o >>= 1) spart += __shfl_xor_sync(0xffffffff, spart, o);
    float inv = 1.0f / (p0 + spart);

    float4 b4 = *(const float4*)(bias + lane * 4);
    acc.x = fmaxf(acc.x * inv + b4.x, 0.f);
    acc.y = fmaxf(acc.y * inv + b4.y, 0.f);
    acc.z = fmaxf(acc.z * inv + b4.z, 0.f);
    acc.w = fmaxf(acc.w * inv + b4.w, 0.f);
    *(float4*)(Ho + (size_t)i * HIDD + lane * 4) = acc;
}

// ---------------- GCN GEMM: warp computes 4 rows x 64 cols, f32x2 FMA ----------------
__global__ void gemm_gcn_k(const float* __restrict__ X, const float* __restrict__ W) {
    __shared__ float2 sx[8][4 * HIDD];
    int warp = threadIdx.x >> 5, lane = threadIdx.x & 31;
    int row0 = (blockIdx.x * 8 + warp) * 4;
    if (row0 >= NN) return;

    for (int t = lane; t < 4 * HIDD; t += 32) {
        float v = X[(size_t)row0 * HIDD + t];
        sx[warp][t] = make_float2(v, v);
    }
    __syncwarp();

    u64 a0 = 0, a1 = 0, a2 = 0, a3 = 0;
    const u64* sx0 = (const u64*)&sx[warp][0];
    const u64* sx1 = (const u64*)&sx[warp][HIDD];
    const u64* sx2p = (const u64*)&sx[warp][2 * HIDD];
    const u64* sx3 = (const u64*)&sx[warp][3 * HIDD];
#pragma unroll 4
    for (int k = 0; k < HIDD; k++) {
        float2 w = *(const float2*)(W + k * OUTD + lane * 2);
        u64 wp = pack2(w.x, w.y);
        FMA2(a0, sx0[k], wp);
        FMA2(a1, sx1[k], wp);
        FMA2(a2, sx2p[k], wp);
        FMA2(a3, sx3[k], wp);
    }
    u64 accs[4] = {a0, a1, a2, a3};
#pragma unroll
    for (int r = 0; r < 4; r++) {
        float2 f = unpack2(accs[r]);
        g_g16[(size_t)(row0 + r) * (OUTD/2) + lane] = __floats2half2_rn(f.x, f.y);
    }
}

__global__ void agg_gcn_k(const float* __restrict__ b4) {
    int warp = threadIdx.x >> 5, lane = threadIdx.x & 31;
    int i = blockIdx.x * 8 + warp;
    if (i >= NN) return;
    int r0 = g_rowptr[i], r1 = g_rowptr[i + 1];
    float di = g_dinv[i];

    float2 gi = __half22float2(g_g16[(size_t)i * (OUTD/2) + lane]);
    float w0 = di * di;
    float2 acc; acc.x = w0 * gi.x; acc.y = w0 * gi.y;

    for (int base = r0; base < r1; base += 32) {
        int j = base + lane;
        int src = 0; float wj = 0.f;
        if (j < r1) {
            src = g_col[j];
            wj = di * g_dinv[src];
        }
        int cnt = r1 - base; if (cnt > 32) cnt = 32;
#pragma unroll 4
        for (int t = 0; t < cnt; t++) {
            float w = __shfl_sync(0xffffffff, wj, t);
            int sj  = __shfl_sync(0xffffffff, src, t);
            float2 gs = __half22float2(g_g16[(size_t)sj * (OUTD/2) + lane]);
            acc.x += w * gs.x; acc.y += w * gs.y;
        }
    }
    float2 bb = *(const float2*)(b4 + lane * 2);
    acc.x += bb.x; acc.y += bb.y;
    *(float2*)(g_z + (size_t)i * OUTD + lane * 2) = acc;
}

// ---------------- link decode: warp per label edge ----------------
__global__ void decode_k(const int* __restrict__ eli, float* __restrict__ out) {
    int warp = threadIdx.x >> 5, lane = threadIdx.x & 31;
    int l = blockIdx.x * 8 + warp;
    if (l >= NLL) return;
    int a = eli[l], b = eli[NLL + l];
    float2 za = *(const float2*)(g_z + (size_t)a * OUTD + lane * 2);
    float2 zb = *(const float2*)(g_z + (size_t)b * OUTD + lane * 2);
    float d = za.x * zb.x + za.y * zb.y;
#pragma unroll
    for (int o = 16; o; o >>= 1) d += __shfl_xor_sync(0xffffffff, d, o);
    if (lane == 0) out[l] = d;
}

// ---------------- launch ----------------
extern "C" void kernel_launch(void* const* d_in, const int* in_sizes, int n_in,
                              void* d_out, int out_size) {
    const float* x    = (const float*)d_in[0];
    const int*   ei   = (const int*)d_in[1];
    const int*   eli  = (const int*)d_in[2];
    const float* W1  = (const float*)d_in[3];
    const float* a1s = (const float*)d_in[4];
    const float* a1d = (const float*)d_in[5];
    const float* b1  = (const float*)d_in[6];
    const float* W2  = (const float*)d_in[7];
    const float* a2s = (const float*)d_in[8];
    const float* a2d = (const float*)d_in[9];
    const float* b2  = (const float*)d_in[10];
    const float* W3  = (const float*)d_in[11];
    const float* a3s = (const float*)d_in[12];
    const float* a3d = (const float*)d_in[13];
    const float* b3  = (const float*)d_in[14];
    const float* W4  = (const float*)d_in[15];
    const float* b4  = (const float*)d_in[16];

    float* hF;
    cudaGetSymbolAddress((void**)&hF, g_hF);

    const int* src = ei;
    const int* dst = ei + EE;

    // CSR build
    zero_cnt_k<<<(NN + 255) / 256, 256>>>();
    count_k<<<(EE + 255) / 256, 256>>>(dst);
    scan_k<<<1, 1024>>>();
    scatter_k<<<(EE + 255) / 256, 256>>>(src, dst);

    int gb_gemm = (NN + 31) / 32;  // 8 warps x 4 rows per block
    int gb_node = (NN + 7) / 8;    // warp per node

    gemm_gat_k<<<gb_gemm, 256>>>(x,  W1, a1s, a1d);
    agg_gat_k <<<gb_node, 256>>>(b1, hF);
    gemm_gat_k<<<gb_gemm, 256>>>(hF, W2, a2s, a2d);
    agg_gat_k <<<gb_node, 256>>>(b2, hF);
    gemm_gat_k<<<gb_gemm, 256>>>(hF, W3, a3s, a3d);
    agg_gat_k <<<gb_node, 256>>>(b3, hF);
    gemm_gcn_k<<<gb_gemm, 256>>>(hF, W4);
    agg_gcn_k <<<gb_node, 256>>>(b4);
    decode_k<<<(NLL + 7) / 8, 256>>>(eli, (float*)d_out);
}